// round 12
// baseline (speedup 1.0000x reference)
#include <cuda_runtime.h>
#include <cuda_bf16.h>
#include <cuda_fp16.h>
#include <cstdint>

#define BB 2
#define SS 2048
#define DM 2048
#define HH 16
#define HD 128
#define NROWS (BB*SS)

// ---------------------------------------------------------------------------
// Helpers (plain sm_80-era PTX only: ldmatrix / mma.sync / cp.async)
// ---------------------------------------------------------------------------
__device__ __forceinline__ uint32_t smem_to_u32(const void* p) {
    uint32_t a;
    asm("{ .reg .u64 t; cvta.to.shared.u64 t, %1; cvt.u32.u64 %0, t; }" : "=r"(a) : "l"(p));
    return a;
}
#define SWZ128(off) ((off) ^ (((off) >> 3) & 0x70))
#define SWZ256(off) ((off) ^ ((((off) >> 8) & 7) << 4))

__device__ __forceinline__ void cpa16(uint32_t s, const void* g) {
    asm volatile("cp.async.cg.shared.global [%0], [%1], 16;" :: "r"(s), "l"(g));
}
#define CP_COMMIT() asm volatile("cp.async.commit_group;" ::: "memory")
#define CP_WAIT2()  asm volatile("cp.async.wait_group 2;" ::: "memory")
#define CP_WAIT1()  asm volatile("cp.async.wait_group 1;" ::: "memory")
#define CP_WAIT0()  asm volatile("cp.async.wait_group 0;" ::: "memory")

__device__ __forceinline__ void ldmx4(uint32_t& r0, uint32_t& r1, uint32_t& r2, uint32_t& r3,
                                      uint32_t addr) {
    asm volatile("ldmatrix.sync.aligned.m8n8.x4.shared.b16 {%0,%1,%2,%3}, [%4];"
                 : "=r"(r0), "=r"(r1), "=r"(r2), "=r"(r3) : "r"(addr));
}
__device__ __forceinline__ void ldmx4t(uint32_t& r0, uint32_t& r1, uint32_t& r2, uint32_t& r3,
                                       uint32_t addr) {
    asm volatile("ldmatrix.sync.aligned.m8n8.x4.trans.shared.b16 {%0,%1,%2,%3}, [%4];"
                 : "=r"(r0), "=r"(r1), "=r"(r2), "=r"(r3) : "r"(addr));
}
__device__ __forceinline__ void mma16816f(float* c, const uint32_t* a, const uint32_t* b) {
    asm volatile("mma.sync.aligned.m16n8k16.row.col.f32.f16.f16.f32 "
                 "{%0,%1,%2,%3}, {%4,%5,%6,%7}, {%8,%9}, {%0,%1,%2,%3};"
                 : "+f"(c[0]), "+f"(c[1]), "+f"(c[2]), "+f"(c[3])
                 : "r"(a[0]), "r"(a[1]), "r"(a[2]), "r"(a[3]), "r"(b[0]), "r"(b[1]));
}

__device__ __forceinline__ uint32_t pack_f16(float a, float b) {
    __half2 t = __floats2half2_rn(a, b);
    return *(uint32_t*)&t;
}

// ---------------------------------------------------------------------------
// Device scratch (all GEMM/flash operands single fp16)
// ---------------------------------------------------------------------------
__device__ __align__(256) float g_q[(size_t)BB*HH*SS*HD];
__device__ __align__(256) float g_k[(size_t)BB*HH*SS*HD];
__device__ __align__(256) __half g_xf[(size_t)NROWS*DM];
__device__ __align__(256) __half g_cf[(size_t)NROWS*DM];
__device__ __align__(256) __half g_wqh[DM*DM], g_wkh[DM*DM], g_wvh[DM*DM], g_woh[DM*DM];
__device__ __align__(256) __half g_yf[(size_t)NROWS*DM];
__device__ __align__(256) __half g_qf[(size_t)BB*HH*SS*HD];
__device__ __align__(256) __half g_kf[(size_t)BB*HH*SS*HD];
__device__ __align__(256) __half g_vf[(size_t)BB*HH*SS*HD];

// ---------------------------------------------------------------------------
// Fused fp32 -> fp16 single-RN conversion for all 6 tensors.
// ---------------------------------------------------------------------------
__global__ void cvt6_kernel(const float* __restrict__ x, const float* __restrict__ ctx,
                            const float* __restrict__ Wq, const float* __restrict__ Wk,
                            const float* __restrict__ Wv, const float* __restrict__ Wo)
{
    int bid = blockIdx.x;
    const float* src;
    __half* dst;
    int lb;
    if (bid < 8192)       { src = x;   dst = g_xf;  lb = bid; }
    else if (bid < 16384) { src = ctx; dst = g_cf;  lb = bid - 8192; }
    else if (bid < 20480) { src = Wq;  dst = g_wqh; lb = bid - 16384; }
    else if (bid < 24576) { src = Wk;  dst = g_wkh; lb = bid - 20480; }
    else if (bid < 28672) { src = Wv;  dst = g_wvh; lb = bid - 24576; }
    else                  { src = Wo;  dst = g_woh; lb = bid - 28672; }
    const int i = lb*256 + threadIdx.x;
    float4 v = ((const float4*)src)[i];
    ((uint2*)dst)[i] = make_uint2(pack_f16(v.x, v.y), pack_f16(v.z, v.w));
}

// ---------------------------------------------------------------------------
// 4-stage single-product fp16 GEMM mainloop, 16 warps, warp tile 32x32.
// C = A @ B^T, both single fp16.
// ---------------------------------------------------------------------------
#define KC 64
#define NSTG (DM/KC)
#define A_OFF 0
#define B_OFF 16384
#define STG_BYTES 32768
#define NBUF 4
#define GEMM_DSMEM (NBUF*STG_BYTES + 1024)

__device__ __forceinline__ void gemm_body(
    const __half* __restrict__ Ah, const __half* __restrict__ Bh,
    uint32_t sbase, int m0, int n0, float acc[2][4][4])
{
    const int tid = threadIdx.x;
    const int wid = tid >> 5;
    const int lane = tid & 31;
    const int warp_m = wid >> 2;
    const int warp_n = wid & 3;

    const int prow = tid >> 2;
    const int pq = tid & 3;
    const size_t gA = (size_t)(m0 + prow) * DM + pq * 16;
    const size_t gB = (size_t)(n0 + prow) * DM + pq * 16;
    const uint32_t swp[2] = {
        SWZ128((uint32_t)(prow*128 + (pq*2 + 0)*16)),
        SWZ128((uint32_t)(prow*128 + (pq*2 + 1)*16)) };

    #pragma unroll
    for (int s = 0; s < 3; s++) {
        const uint32_t buf = sbase + s * STG_BYTES;
        const size_t ko = (size_t)s * KC;
        #pragma unroll
        for (int c = 0; c < 2; c++) {
            const size_t go = ko + (size_t)c * 8;
            cpa16(buf + A_OFF + swp[c], Ah + gA + go);
            cpa16(buf + B_OFF + swp[c], Bh + gB + go);
        }
        CP_COMMIT();
    }

    const int a_r = warp_m*32 + (lane & 15);
    const int a_cs = lane >> 4;
    const int b_r = warp_n*32 + ((lane >> 4) << 3) + (lane & 7);
    const int b_cs = (lane >> 3) & 1;

    int sbuf = 0;
    for (int s = 0; s < NSTG; s++) {
        CP_WAIT2();
        __syncthreads();
        if (s + 3 < NSTG) {
            const uint32_t buf = sbase + ((sbuf + 3) & 3) * STG_BYTES;
            const size_t ko = (size_t)(s+3) * KC;
            #pragma unroll
            for (int c = 0; c < 2; c++) {
                const size_t go = ko + (size_t)c * 8;
                cpa16(buf + A_OFF + swp[c], Ah + gA + go);
                cpa16(buf + B_OFF + swp[c], Bh + gB + go);
            }
            CP_COMMIT();
        }

        const uint32_t buf = sbase + sbuf * STG_BYTES;
        #pragma unroll
        for (int ks = 0; ks < 4; ks++) {
            const int kc = ks * 2;
            uint32_t ah[2][4], bh[4][2];
            #pragma unroll
            for (int mt = 0; mt < 2; mt++) {
                const uint32_t off = (uint32_t)((a_r + mt*16)*128 + (kc + a_cs)*16);
                ldmx4(ah[mt][0], ah[mt][1], ah[mt][2], ah[mt][3], buf + A_OFF + SWZ128(off));
            }
            #pragma unroll
            for (int np = 0; np < 2; np++) {
                const uint32_t off = (uint32_t)((b_r + np*16)*128 + (kc + b_cs)*16);
                ldmx4(bh[np*2][0], bh[np*2][1], bh[np*2+1][0], bh[np*2+1][1],
                      buf + B_OFF + SWZ128(off));
            }
            #pragma unroll
            for (int mt = 0; mt < 2; mt++)
                #pragma unroll
                for (int nt = 0; nt < 4; nt++)
                    mma16816f(acc[mt][nt], ah[mt], bh[nt]);
        }
        sbuf = (sbuf + 1) & 3;
    }
}

// ---------------------------------------------------------------------------
// Fused Q/K/V projection: blockIdx.z selects operand set + epilogue.
// z=0: Q -> g_q fp32; z=1: K -> g_k fp32; z=2: V -> g_vf fp16.
// ---------------------------------------------------------------------------
__global__ __launch_bounds__(512, 1)
void qkv_kernel()
{
    extern __shared__ char dsm_raw[];
    const uint32_t raw_u = smem_to_u32(dsm_raw);
    const uint32_t sbase = (raw_u + 1023u) & ~1023u;

    const int z = blockIdx.z;
    const __half *Ah, *Bh;
    if (z == 0)      { Ah = g_xf; Bh = g_wqh; }
    else if (z == 1) { Ah = g_cf; Bh = g_wkh; }
    else             { Ah = g_cf; Bh = g_wvh; }

    const int m0 = blockIdx.y * 128;
    const int n0 = blockIdx.x * 128;

    float acc[2][4][4];
    #pragma unroll
    for (int i = 0; i < 2; i++)
        #pragma unroll
        for (int j = 0; j < 4; j++)
            #pragma unroll
            for (int r = 0; r < 4; r++) acc[i][j][r] = 0.f;

    gemm_body(Ah, Bh, sbase, m0, n0, acc);

    const int tid = threadIdx.x;
    const int wid = tid >> 5;
    const int lane = tid & 31;
    const int warp_m = wid >> 2;
    const int warp_n = wid & 3;

    #pragma unroll
    for (int mt = 0; mt < 2; mt++) {
        const int mrow = m0 + warp_m*32 + mt*16 + (lane >> 2);
        #pragma unroll
        for (int half = 0; half < 2; half++) {
            const int m = mrow + half*8;
            const int b = m >> 11, sidx = m & (SS - 1);
            const size_t rb = ((size_t)((b*HH + blockIdx.x)*SS + sidx))*HD;
            #pragma unroll
            for (int nt = 0; nt < 4; nt++) {
                const int nn = warp_n*32 + nt*8 + 2*(lane & 3);
                float vx = half ? acc[mt][nt][2] : acc[mt][nt][0];
                float vy = half ? acc[mt][nt][3] : acc[mt][nt][1];
                if (z == 0) {
                    *(float2*)(g_q + rb + nn) = make_float2(vx, vy);
                } else if (z == 1) {
                    *(float2*)(g_k + rb + nn) = make_float2(vx, vy);
                } else {
                    *(uint32_t*)(g_vf + rb + nn) = pack_f16(vx, vy);
                }
            }
        }
    }
}

// ---------------------------------------------------------------------------
// Output projection: out = y @ Wo^T, fp32 result.
// ---------------------------------------------------------------------------
__global__ __launch_bounds__(512, 1)
void wo_kernel(float* __restrict__ C)
{
    extern __shared__ char dsm_raw[];
    const uint32_t raw_u = smem_to_u32(dsm_raw);
    const uint32_t sbase = (raw_u + 1023u) & ~1023u;

    const int m0 = blockIdx.y * 128;
    const int n0 = blockIdx.x * 128;

    float acc[2][4][4];
    #pragma unroll
    for (int i = 0; i < 2; i++)
        #pragma unroll
        for (int j = 0; j < 4; j++)
            #pragma unroll
            for (int r = 0; r < 4; r++) acc[i][j][r] = 0.f;

    gemm_body(g_yf, g_woh, sbase, m0, n0, acc);

    const int tid = threadIdx.x;
    const int wid = tid >> 5;
    const int lane = tid & 31;
    const int warp_m = wid >> 2;
    const int warp_n = wid & 3;

    #pragma unroll
    for (int mt = 0; mt < 2; mt++) {
        const int mrow = m0 + warp_m*32 + mt*16 + (lane >> 2);
        #pragma unroll
        for (int half = 0; half < 2; half++) {
            const int m = mrow + half*8;
            #pragma unroll
            for (int nt = 0; nt < 4; nt++) {
                const int nn = warp_n*32 + nt*8 + 2*(lane & 3);
                float vx = half ? acc[mt][nt][2] : acc[mt][nt][0];
                float vy = half ? acc[mt][nt][3] : acc[mt][nt][1];
                *(float2*)(C + (size_t)m*DM + n0 + nn) = make_float2(vx, vy);
            }
        }
    }
}

// ---------------------------------------------------------------------------
// RMS norm + RoPE; emits Q and K as single fp16.
// ---------------------------------------------------------------------------
__global__ void rms_rope_kernel(const float* __restrict__ cq, const float* __restrict__ sq,
                                const float* __restrict__ ck, const float* __restrict__ sk,
                                const float* __restrict__ qw, const float* __restrict__ kw)
{
    const int row = blockIdx.x;
    const int isk = blockIdx.y;
    const float* data = isk ? g_k : g_q;
    const float* cp = isk ? ck : cq;
    const float* sp = isk ? sk : sq;
    const float* w  = isk ? kw : qw;
    __half* outp = isk ? g_kf : g_qf;
    const int tid = threadIdx.x;
    const int s = row % SS;
    const int b = row / (HH*SS);

    __shared__ float smv[HD];
    __shared__ float red[4];
    float v = data[(size_t)row*HD + tid];
    float s2 = v*v;
    #pragma unroll
    for (int o = 16; o; o >>= 1) s2 += __shfl_xor_sync(0xffffffffu, s2, o);
    if ((tid & 31) == 0) red[tid >> 5] = s2;
    __syncthreads();
    const float var = (red[0]+red[1]+red[2]+red[3]) * (1.0f/HD);
    const float qn = v * rsqrtf(var + 1e-6f) * w[tid];
    smv[tid] = qn;
    __syncthreads();
    const float rot = (tid < 64) ? -smv[tid+64] : smv[tid-64];
    const size_t ci = ((size_t)b*SS + s)*HD + tid;
    const float val = qn * cp[ci] + rot * sp[ci];
    outp[(size_t)row*HD + tid] = __float2half_rn(val);
}

// ---------------------------------------------------------------------------
// Flash attention, single fp16 operands (Q, K, P, V); y emitted single fp16.
// CTA = 128 queries, 8 warps x 16 rows; K/V double-buffered.
// ---------------------------------------------------------------------------
#define FB_Q 0
#define FB_ST 32768
#define ST_SZ 32768
#define T_K 0
#define T_V 16384
#define NKB (SS/64)
#define FLASH_DSMEM (FB_ST + 2*ST_SZ + 1024)

__global__ __launch_bounds__(256, 1)
void flash_mma()
{
    extern __shared__ char fsm_raw[];
    const uint32_t raw_u = smem_to_u32(fsm_raw);
    const uint32_t sb0 = (raw_u + 1023u) & ~1023u;
    char* bp = fsm_raw + (sb0 - raw_u);

    const int tid = threadIdx.x;
    const int wid = tid >> 5;
    const int lane = tid & 31;
    const int qb = blockIdx.x;
    const int bh = blockIdx.y;

    const size_t base = (size_t)bh * SS * HD;
    const char* Qf = (const char*)(g_qf + base + (size_t)qb * 128 * HD);
    const char* Kf = (const char*)(g_kf + base);
    const char* Vf = (const char*)(g_vf + base);

    #pragma unroll
    for (int i = 0; i < 8; i++) {
        const int idx = tid + i*256;
        const int row = idx >> 4, c = idx & 15;
        const uint32_t d = SWZ256((uint32_t)(row*256 + c*16));
        *(uint4*)(bp + FB_Q + d) = *(const uint4*)(Qf + (size_t)row*256 + c*16);
    }

    {
        const uint32_t sb = sb0 + FB_ST;
        #pragma unroll
        for (int j = 0; j < 4; j++) {
            const int idx = tid + j*256;
            const int row = idx >> 4, c = idx & 15;
            const uint32_t d = SWZ256((uint32_t)(row*256 + c*16));
            const size_t go = (size_t)row*256 + c*16;
            cpa16(sb + T_K + d, Kf + go);
            cpa16(sb + T_V + d, Vf + go);
        }
        CP_COMMIT();
    }

    float sacc[8][4];
    float oacc[16][4];
    #pragma unroll
    for (int i = 0; i < 16; i++)
        #pragma unroll
        for (int r = 0; r < 4; r++) oacc[i][r] = 0.f;
    float m0 = -1e30f, m1 = -1e30f, l0 = 0.f, l1 = 0.f;

    const int w16 = wid * 16;
    const uint32_t qa_off = (uint32_t)((w16 + (lane & 15))*256 + (lane >> 4)*16);
    const uint32_t kb_row = (uint32_t)(((lane >> 4) << 3) + (lane & 7));
    const uint32_t kb_cs = (uint32_t)(((lane >> 3) & 1) * 16);
    const uint32_t vb_row = (uint32_t)((lane & 7) + (((lane >> 3) & 1) << 3));
    const uint32_t vb_cs = (uint32_t)((lane >> 4) * 16);
    const float sc = 0.08838834764831845f;

    for (int kb = 0; kb < NKB; kb++) {
        if (kb > 0) __syncthreads();
        if (kb + 1 < NKB) {
            const uint32_t sb = sb0 + FB_ST + ((kb+1) & 1) * ST_SZ;
            const size_t kbase = (size_t)(kb+1) * 64 * 256;
            #pragma unroll
            for (int j = 0; j < 4; j++) {
                const int idx = tid + j*256;
                const int row = idx >> 4, c = idx & 15;
                const uint32_t d = SWZ256((uint32_t)(row*256 + c*16));
                const size_t go = kbase + (size_t)row*256 + c*16;
                cpa16(sb + T_K + d, Kf + go);
                cpa16(sb + T_V + d, Vf + go);
            }
            CP_COMMIT();
            CP_WAIT1();
        } else {
            CP_WAIT0();
        }
        __syncthreads();

        const uint32_t sb = sb0 + FB_ST + (kb & 1) * ST_SZ;

        #pragma unroll
        for (int i = 0; i < 8; i++)
            #pragma unroll
            for (int r = 0; r < 4; r++) sacc[i][r] = 0.f;

        #pragma unroll
        for (int kk = 0; kk < 8; kk++) {
            uint32_t q4[4];
            const uint32_t qa = sb0 + FB_Q + SWZ256(qa_off + (uint32_t)kk*32);
            ldmx4(q4[0], q4[1], q4[2], q4[3], qa);
            #pragma unroll
            for (int n16 = 0; n16 < 4; n16++) {
                uint32_t kh4[4];
                const uint32_t ka = sb + T_K +
                    SWZ256((uint32_t)((n16*16 + kb_row)*256 + kk*32 + kb_cs));
                ldmx4(kh4[0], kh4[1], kh4[2], kh4[3], ka);
                mma16816f(sacc[2*n16],   q4, &kh4[0]);
                mma16816f(sacc[2*n16+1], q4, &kh4[2]);
            }
        }

        #pragma unroll
        for (int i = 0; i < 8; i++)
            #pragma unroll
            for (int r = 0; r < 4; r++) sacc[i][r] *= sc;

        float nm0 = -1e30f, nm1 = -1e30f;
        #pragma unroll
        for (int i = 0; i < 8; i++) {
            nm0 = fmaxf(nm0, fmaxf(sacc[i][0], sacc[i][1]));
            nm1 = fmaxf(nm1, fmaxf(sacc[i][2], sacc[i][3]));
        }
        nm0 = fmaxf(nm0, __shfl_xor_sync(0xffffffffu, nm0, 1));
        nm0 = fmaxf(nm0, __shfl_xor_sync(0xffffffffu, nm0, 2));
        nm1 = fmaxf(nm1, __shfl_xor_sync(0xffffffffu, nm1, 1));
        nm1 = fmaxf(nm1, __shfl_xor_sync(0xffffffffu, nm1, 2));
        const float mn0 = fmaxf(m0, nm0), mn1 = fmaxf(m1, nm1);
        const float a0 = __expf(m0 - mn0), a1 = __expf(m1 - mn1);
        m0 = mn0; m1 = mn1;
        float ls0 = 0.f, ls1 = 0.f;
        #pragma unroll
        for (int i = 0; i < 8; i++) {
            float p0 = __expf(sacc[i][0] - m0); sacc[i][0] = p0; ls0 += p0;
            float p1 = __expf(sacc[i][1] - m0); sacc[i][1] = p1; ls0 += p1;
            float p2 = __expf(sacc[i][2] - m1); sacc[i][2] = p2; ls1 += p2;
            float p3 = __expf(sacc[i][3] - m1); sacc[i][3] = p3; ls1 += p3;
        }
        ls0 += __shfl_xor_sync(0xffffffffu, ls0, 1);
        ls0 += __shfl_xor_sync(0xffffffffu, ls0, 2);
        ls1 += __shfl_xor_sync(0xffffffffu, ls1, 1);
        ls1 += __shfl_xor_sync(0xffffffffu, ls1, 2);
        l0 = l0*a0 + ls0;
        l1 = l1*a1 + ls1;
        #pragma unroll
        for (int i = 0; i < 16; i++) {
            oacc[i][0] *= a0; oacc[i][1] *= a0;
            oacc[i][2] *= a1; oacc[i][3] *= a1;
        }

        #pragma unroll
        for (int kk = 0; kk < 4; kk++) {
            uint32_t ph[4];
            ph[0] = pack_f16(sacc[2*kk][0],   sacc[2*kk][1]);
            ph[1] = pack_f16(sacc[2*kk][2],   sacc[2*kk][3]);
            ph[2] = pack_f16(sacc[2*kk+1][0], sacc[2*kk+1][1]);
            ph[3] = pack_f16(sacc[2*kk+1][2], sacc[2*kk+1][3]);
            #pragma unroll
            for (int n16 = 0; n16 < 8; n16++) {
                uint32_t vh4[4];
                const uint32_t va = sb + T_V +
                    SWZ256((uint32_t)((kk*16 + vb_row)*256 + n16*32 + vb_cs));
                ldmx4t(vh4[0], vh4[1], vh4[2], vh4[3], va);
                mma16816f(oacc[2*n16],   ph, &vh4[0]);
                mma16816f(oacc[2*n16+1], ph, &vh4[2]);
            }
        }
    }

    // epilogue: y as single fp16, (B, S, H, hd) layout
    const int b = bh / HH, h = bh % HH;
    const int g = lane >> 2;
    const int col0 = (lane & 3) * 2;
    const float li0 = 1.0f / l0, li1 = 1.0f / l1;
    const int s0 = qb*128 + w16 + g;
    const size_t yb0 = ((size_t)(b*SS + s0)*HH + h)*HD;
    const size_t yb1 = ((size_t)(b*SS + s0 + 8)*HH + h)*HD;
    #pragma unroll
    for (int nt = 0; nt < 16; nt++) {
        const int c = nt*8 + col0;
        *(uint32_t*)(g_yf + yb0 + c) = pack_f16(oacc[nt][0]*li0, oacc[nt][1]*li0);
        *(uint32_t*)(g_yf + yb1 + c) = pack_f16(oacc[nt][2]*li1, oacc[nt][3]*li1);
    }
}

// ---------------------------------------------------------------------------
extern "C" void kernel_launch(void* const* d_in, const int* in_sizes, int n_in,
                              void* d_out, int out_size)
{
    const float* x   = (const float*)d_in[0];
    const float* ctx = (const float*)d_in[1];
    const float* cq  = (const float*)d_in[2];
    const float* sq  = (const float*)d_in[3];
    const float* ck  = (const float*)d_in[4];
    const float* sk  = (const float*)d_in[5];
    const float* Wq  = (const float*)d_in[6];
    const float* Wk  = (const float*)d_in[7];
    const float* Wv  = (const float*)d_in[8];
    const float* Wo  = (const float*)d_in[9];
    const float* qw  = (const float*)d_in[10];
    const float* kw  = (const float*)d_in[11];
    float* out = (float*)d_out;

    cudaFuncSetAttribute(qkv_kernel, cudaFuncAttributeMaxDynamicSharedMemorySize, GEMM_DSMEM);
    cudaFuncSetAttribute(wo_kernel,  cudaFuncAttributeMaxDynamicSharedMemorySize, GEMM_DSMEM);
    cudaFuncSetAttribute(flash_mma,  cudaFuncAttributeMaxDynamicSharedMemorySize, FLASH_DSMEM);

    cvt6_kernel<<<32768, 256>>>(x, ctx, Wq, Wk, Wv, Wo);

    dim3 gq3(DM/128, NROWS/128, 3);     // (16, 32, 3)
    qkv_kernel<<<gq3, 512, GEMM_DSMEM>>>();
    rms_rope_kernel<<<dim3(BB*HH*SS, 2), HD>>>(cq, sq, ck, sk, qw, kw);
    flash_mma<<<dim3(SS/128, BB*HH), 256, FLASH_DSMEM>>>();
    dim3 gg(DM/128, NROWS/128);         // (16, 32)
    wo_kernel<<<gg, 512, GEMM_DSMEM>>>(out);
}

// round 13
// speedup vs baseline: 1.5034x; 1.5034x over previous
#include <cuda_runtime.h>
#include <cuda_bf16.h>
#include <cuda_fp16.h>
#include <cstdint>

#define BB 2
#define SS 2048
#define DM 2048
#define HH 16
#define HD 128
#define NROWS (BB*SS)

// ---------------------------------------------------------------------------
// Helpers (plain sm_80-era PTX only: ldmatrix / mma.sync / cp.async)
// ---------------------------------------------------------------------------
__device__ __forceinline__ uint32_t smem_to_u32(const void* p) {
    uint32_t a;
    asm("{ .reg .u64 t; cvta.to.shared.u64 t, %1; cvt.u32.u64 %0, t; }" : "=r"(a) : "l"(p));
    return a;
}
#define SWZ128(off) ((off) ^ (((off) >> 3) & 0x70))
#define SWZ256(off) ((off) ^ ((((off) >> 8) & 7) << 4))

__device__ __forceinline__ void cpa16(uint32_t s, const void* g) {
    asm volatile("cp.async.cg.shared.global [%0], [%1], 16;" :: "r"(s), "l"(g));
}
#define CP_COMMIT() asm volatile("cp.async.commit_group;" ::: "memory")
#define CP_WAIT2()  asm volatile("cp.async.wait_group 2;" ::: "memory")
#define CP_WAIT1()  asm volatile("cp.async.wait_group 1;" ::: "memory")
#define CP_WAIT0()  asm volatile("cp.async.wait_group 0;" ::: "memory")

__device__ __forceinline__ void ldmx4(uint32_t& r0, uint32_t& r1, uint32_t& r2, uint32_t& r3,
                                      uint32_t addr) {
    asm volatile("ldmatrix.sync.aligned.m8n8.x4.shared.b16 {%0,%1,%2,%3}, [%4];"
                 : "=r"(r0), "=r"(r1), "=r"(r2), "=r"(r3) : "r"(addr));
}
__device__ __forceinline__ void ldmx4t(uint32_t& r0, uint32_t& r1, uint32_t& r2, uint32_t& r3,
                                       uint32_t addr) {
    asm volatile("ldmatrix.sync.aligned.m8n8.x4.trans.shared.b16 {%0,%1,%2,%3}, [%4];"
                 : "=r"(r0), "=r"(r1), "=r"(r2), "=r"(r3) : "r"(addr));
}
__device__ __forceinline__ void mma16816f(float* c, const uint32_t* a, const uint32_t* b) {
    asm volatile("mma.sync.aligned.m16n8k16.row.col.f32.f16.f16.f32 "
                 "{%0,%1,%2,%3}, {%4,%5,%6,%7}, {%8,%9}, {%0,%1,%2,%3};"
                 : "+f"(c[0]), "+f"(c[1]), "+f"(c[2]), "+f"(c[3])
                 : "r"(a[0]), "r"(a[1]), "r"(a[2]), "r"(a[3]), "r"(b[0]), "r"(b[1]));
}

__device__ __forceinline__ uint32_t pack_f16(float a, float b) {
    __half2 t = __floats2half2_rn(a, b);
    return *(uint32_t*)&t;
}

// ---------------------------------------------------------------------------
// Device scratch (all GEMM/flash operands single fp16)
// ---------------------------------------------------------------------------
__device__ __align__(256) float g_q[(size_t)BB*HH*SS*HD];
__device__ __align__(256) float g_k[(size_t)BB*HH*SS*HD];
__device__ __align__(256) __half g_xf[(size_t)NROWS*DM];
__device__ __align__(256) __half g_cf[(size_t)NROWS*DM];
__device__ __align__(256) __half g_wqh[DM*DM], g_wkh[DM*DM], g_wvh[DM*DM], g_woh[DM*DM];
__device__ __align__(256) __half g_yf[(size_t)NROWS*DM];
__device__ __align__(256) __half g_qf[(size_t)BB*HH*SS*HD];
__device__ __align__(256) __half g_kf[(size_t)BB*HH*SS*HD];
__device__ __align__(256) __half g_vf[(size_t)BB*HH*SS*HD];

// ---------------------------------------------------------------------------
// Fused fp32 -> fp16 single-RN conversion for all 6 tensors.
// ---------------------------------------------------------------------------
__global__ void cvt6_kernel(const float* __restrict__ x, const float* __restrict__ ctx,
                            const float* __restrict__ Wq, const float* __restrict__ Wk,
                            const float* __restrict__ Wv, const float* __restrict__ Wo)
{
    int bid = blockIdx.x;
    const float* src;
    __half* dst;
    int lb;
    if (bid < 8192)       { src = x;   dst = g_xf;  lb = bid; }
    else if (bid < 16384) { src = ctx; dst = g_cf;  lb = bid - 8192; }
    else if (bid < 20480) { src = Wq;  dst = g_wqh; lb = bid - 16384; }
    else if (bid < 24576) { src = Wk;  dst = g_wkh; lb = bid - 20480; }
    else if (bid < 28672) { src = Wv;  dst = g_wvh; lb = bid - 24576; }
    else                  { src = Wo;  dst = g_woh; lb = bid - 28672; }
    const int i = lb*256 + threadIdx.x;
    float4 v = ((const float4*)src)[i];
    ((uint2*)dst)[i] = make_uint2(pack_f16(v.x, v.y), pack_f16(v.z, v.w));
}

// ---------------------------------------------------------------------------
// 4-stage single-product fp16 GEMM mainloop, 16 warps, warp tile 32x32.
// C = A @ B^T, both single fp16.
// ---------------------------------------------------------------------------
#define KC 64
#define NSTG (DM/KC)
#define A_OFF 0
#define B_OFF 16384
#define STG_BYTES 32768
#define NBUF 4
#define GEMM_DSMEM (NBUF*STG_BYTES + 1024)

__device__ __forceinline__ void gemm_body(
    const __half* __restrict__ Ah, const __half* __restrict__ Bh,
    uint32_t sbase, int m0, int n0, float acc[2][4][4])
{
    const int tid = threadIdx.x;
    const int wid = tid >> 5;
    const int lane = tid & 31;
    const int warp_m = wid >> 2;
    const int warp_n = wid & 3;

    const int prow = tid >> 2;
    const int pq = tid & 3;
    const size_t gA = (size_t)(m0 + prow) * DM + pq * 16;
    const size_t gB = (size_t)(n0 + prow) * DM + pq * 16;
    const uint32_t swp[2] = {
        SWZ128((uint32_t)(prow*128 + (pq*2 + 0)*16)),
        SWZ128((uint32_t)(prow*128 + (pq*2 + 1)*16)) };

    #pragma unroll
    for (int s = 0; s < 3; s++) {
        const uint32_t buf = sbase + s * STG_BYTES;
        const size_t ko = (size_t)s * KC;
        #pragma unroll
        for (int c = 0; c < 2; c++) {
            const size_t go = ko + (size_t)c * 8;
            cpa16(buf + A_OFF + swp[c], Ah + gA + go);
            cpa16(buf + B_OFF + swp[c], Bh + gB + go);
        }
        CP_COMMIT();
    }

    const int a_r = warp_m*32 + (lane & 15);
    const int a_cs = lane >> 4;
    const int b_r = warp_n*32 + ((lane >> 4) << 3) + (lane & 7);
    const int b_cs = (lane >> 3) & 1;

    int sbuf = 0;
    for (int s = 0; s < NSTG; s++) {
        CP_WAIT2();
        __syncthreads();
        if (s + 3 < NSTG) {
            const uint32_t buf = sbase + ((sbuf + 3) & 3) * STG_BYTES;
            const size_t ko = (size_t)(s+3) * KC;
            #pragma unroll
            for (int c = 0; c < 2; c++) {
                const size_t go = ko + (size_t)c * 8;
                cpa16(buf + A_OFF + swp[c], Ah + gA + go);
                cpa16(buf + B_OFF + swp[c], Bh + gB + go);
            }
            CP_COMMIT();
        }

        const uint32_t buf = sbase + sbuf * STG_BYTES;
        #pragma unroll
        for (int ks = 0; ks < 4; ks++) {
            const int kc = ks * 2;
            uint32_t ah[2][4], bh[4][2];
            #pragma unroll
            for (int mt = 0; mt < 2; mt++) {
                const uint32_t off = (uint32_t)((a_r + mt*16)*128 + (kc + a_cs)*16);
                ldmx4(ah[mt][0], ah[mt][1], ah[mt][2], ah[mt][3], buf + A_OFF + SWZ128(off));
            }
            #pragma unroll
            for (int np = 0; np < 2; np++) {
                const uint32_t off = (uint32_t)((b_r + np*16)*128 + (kc + b_cs)*16);
                ldmx4(bh[np*2][0], bh[np*2][1], bh[np*2+1][0], bh[np*2+1][1],
                      buf + B_OFF + SWZ128(off));
            }
            #pragma unroll
            for (int mt = 0; mt < 2; mt++)
                #pragma unroll
                for (int nt = 0; nt < 4; nt++)
                    mma16816f(acc[mt][nt], ah[mt], bh[nt]);
        }
        sbuf = (sbuf + 1) & 3;
    }
}

// ---------------------------------------------------------------------------
// Fused Q/K/V projection: blockIdx.z selects operand set + epilogue.
// z=0: Q -> g_q fp32; z=1: K -> g_k fp32; z=2: V -> g_vf fp16.
// ---------------------------------------------------------------------------
__global__ __launch_bounds__(512, 1)
void qkv_kernel()
{
    extern __shared__ char dsm_raw[];
    const uint32_t raw_u = smem_to_u32(dsm_raw);
    const uint32_t sbase = (raw_u + 1023u) & ~1023u;

    const int z = blockIdx.z;
    const __half *Ah, *Bh;
    if (z == 0)      { Ah = g_xf; Bh = g_wqh; }
    else if (z == 1) { Ah = g_cf; Bh = g_wkh; }
    else             { Ah = g_cf; Bh = g_wvh; }

    const int m0 = blockIdx.y * 128;
    const int n0 = blockIdx.x * 128;

    float acc[2][4][4];
    #pragma unroll
    for (int i = 0; i < 2; i++)
        #pragma unroll
        for (int j = 0; j < 4; j++)
            #pragma unroll
            for (int r = 0; r < 4; r++) acc[i][j][r] = 0.f;

    gemm_body(Ah, Bh, sbase, m0, n0, acc);

    const int tid = threadIdx.x;
    const int wid = tid >> 5;
    const int lane = tid & 31;
    const int warp_m = wid >> 2;
    const int warp_n = wid & 3;

    #pragma unroll
    for (int mt = 0; mt < 2; mt++) {
        const int mrow = m0 + warp_m*32 + mt*16 + (lane >> 2);
        #pragma unroll
        for (int half = 0; half < 2; half++) {
            const int m = mrow + half*8;
            const int b = m >> 11, sidx = m & (SS - 1);
            const size_t rb = ((size_t)((b*HH + blockIdx.x)*SS + sidx))*HD;
            #pragma unroll
            for (int nt = 0; nt < 4; nt++) {
                const int nn = warp_n*32 + nt*8 + 2*(lane & 3);
                float vx = half ? acc[mt][nt][2] : acc[mt][nt][0];
                float vy = half ? acc[mt][nt][3] : acc[mt][nt][1];
                if (z == 0) {
                    *(float2*)(g_q + rb + nn) = make_float2(vx, vy);
                } else if (z == 1) {
                    *(float2*)(g_k + rb + nn) = make_float2(vx, vy);
                } else {
                    *(uint32_t*)(g_vf + rb + nn) = pack_f16(vx, vy);
                }
            }
        }
    }
}

// ---------------------------------------------------------------------------
// Output projection: out = y @ Wo^T, fp32 result.
// ---------------------------------------------------------------------------
__global__ __launch_bounds__(512, 1)
void wo_kernel(float* __restrict__ C)
{
    extern __shared__ char dsm_raw[];
    const uint32_t raw_u = smem_to_u32(dsm_raw);
    const uint32_t sbase = (raw_u + 1023u) & ~1023u;

    const int m0 = blockIdx.y * 128;
    const int n0 = blockIdx.x * 128;

    float acc[2][4][4];
    #pragma unroll
    for (int i = 0; i < 2; i++)
        #pragma unroll
        for (int j = 0; j < 4; j++)
            #pragma unroll
            for (int r = 0; r < 4; r++) acc[i][j][r] = 0.f;

    gemm_body(g_yf, g_woh, sbase, m0, n0, acc);

    const int tid = threadIdx.x;
    const int wid = tid >> 5;
    const int lane = tid & 31;
    const int warp_m = wid >> 2;
    const int warp_n = wid & 3;

    #pragma unroll
    for (int mt = 0; mt < 2; mt++) {
        const int mrow = m0 + warp_m*32 + mt*16 + (lane >> 2);
        #pragma unroll
        for (int half = 0; half < 2; half++) {
            const int m = mrow + half*8;
            #pragma unroll
            for (int nt = 0; nt < 4; nt++) {
                const int nn = warp_n*32 + nt*8 + 2*(lane & 3);
                float vx = half ? acc[mt][nt][2] : acc[mt][nt][0];
                float vy = half ? acc[mt][nt][3] : acc[mt][nt][1];
                *(float2*)(C + (size_t)m*DM + n0 + nn) = make_float2(vx, vy);
            }
        }
    }
}

// ---------------------------------------------------------------------------
// RMS norm + RoPE; emits Q and K as single fp16.
// ---------------------------------------------------------------------------
__global__ void rms_rope_kernel(const float* __restrict__ cq, const float* __restrict__ sq,
                                const float* __restrict__ ck, const float* __restrict__ sk,
                                const float* __restrict__ qw, const float* __restrict__ kw)
{
    const int row = blockIdx.x;
    const int isk = blockIdx.y;
    const float* data = isk ? g_k : g_q;
    const float* cp = isk ? ck : cq;
    const float* sp = isk ? sk : sq;
    const float* w  = isk ? kw : qw;
    __half* outp = isk ? g_kf : g_qf;
    const int tid = threadIdx.x;
    const int s = row % SS;
    const int b = row / (HH*SS);

    __shared__ float smv[HD];
    __shared__ float red[4];
    float v = data[(size_t)row*HD + tid];
    float s2 = v*v;
    #pragma unroll
    for (int o = 16; o; o >>= 1) s2 += __shfl_xor_sync(0xffffffffu, s2, o);
    if ((tid & 31) == 0) red[tid >> 5] = s2;
    __syncthreads();
    const float var = (red[0]+red[1]+red[2]+red[3]) * (1.0f/HD);
    const float qn = v * rsqrtf(var + 1e-6f) * w[tid];
    smv[tid] = qn;
    __syncthreads();
    const float rot = (tid < 64) ? -smv[tid+64] : smv[tid-64];
    const size_t ci = ((size_t)b*SS + s)*HD + tid;
    const float val = qn * cp[ci] + rot * sp[ci];
    outp[(size_t)row*HD + tid] = __float2half_rn(val);
}

// ---------------------------------------------------------------------------
// Flash attention, single fp16 operands (Q, K, P, V); y emitted single fp16.
// CTA = 128 queries, 8 warps x 16 rows; K/V double-buffered.
// ---------------------------------------------------------------------------
#define FB_Q 0
#define FB_ST 32768
#define ST_SZ 32768
#define T_K 0
#define T_V 16384
#define NKB (SS/64)
#define FLASH_DSMEM (FB_ST + 2*ST_SZ + 1024)

__global__ __launch_bounds__(256, 1)
void flash_mma()
{
    extern __shared__ char fsm_raw[];
    const uint32_t raw_u = smem_to_u32(fsm_raw);
    const uint32_t sb0 = (raw_u + 1023u) & ~1023u;
    char* bp = fsm_raw + (sb0 - raw_u);

    const int tid = threadIdx.x;
    const int wid = tid >> 5;
    const int lane = tid & 31;
    const int qb = blockIdx.x;
    const int bh = blockIdx.y;

    const size_t base = (size_t)bh * SS * HD;
    const char* Qf = (const char*)(g_qf + base + (size_t)qb * 128 * HD);
    const char* Kf = (const char*)(g_kf + base);
    const char* Vf = (const char*)(g_vf + base);

    #pragma unroll
    for (int i = 0; i < 8; i++) {
        const int idx = tid + i*256;
        const int row = idx >> 4, c = idx & 15;
        const uint32_t d = SWZ256((uint32_t)(row*256 + c*16));
        *(uint4*)(bp + FB_Q + d) = *(const uint4*)(Qf + (size_t)row*256 + c*16);
    }

    {
        const uint32_t sb = sb0 + FB_ST;
        #pragma unroll
        for (int j = 0; j < 4; j++) {
            const int idx = tid + j*256;
            const int row = idx >> 4, c = idx & 15;
            const uint32_t d = SWZ256((uint32_t)(row*256 + c*16));
            const size_t go = (size_t)row*256 + c*16;
            cpa16(sb + T_K + d, Kf + go);
            cpa16(sb + T_V + d, Vf + go);
        }
        CP_COMMIT();
    }

    float sacc[8][4];
    float oacc[16][4];
    #pragma unroll
    for (int i = 0; i < 16; i++)
        #pragma unroll
        for (int r = 0; r < 4; r++) oacc[i][r] = 0.f;
    float m0 = -1e30f, m1 = -1e30f, l0 = 0.f, l1 = 0.f;

    const int w16 = wid * 16;
    const uint32_t qa_off = (uint32_t)((w16 + (lane & 15))*256 + (lane >> 4)*16);
    const uint32_t kb_row = (uint32_t)(((lane >> 4) << 3) + (lane & 7));
    const uint32_t kb_cs = (uint32_t)(((lane >> 3) & 1) * 16);
    const uint32_t vb_row = (uint32_t)((lane & 7) + (((lane >> 3) & 1) << 3));
    const uint32_t vb_cs = (uint32_t)((lane >> 4) * 16);
    const float sc = 0.08838834764831845f;

    for (int kb = 0; kb < NKB; kb++) {
        if (kb > 0) __syncthreads();
        if (kb + 1 < NKB) {
            const uint32_t sb = sb0 + FB_ST + ((kb+1) & 1) * ST_SZ;
            const size_t kbase = (size_t)(kb+1) * 64 * 256;
            #pragma unroll
            for (int j = 0; j < 4; j++) {
                const int idx = tid + j*256;
                const int row = idx >> 4, c = idx & 15;
                const uint32_t d = SWZ256((uint32_t)(row*256 + c*16));
                const size_t go = kbase + (size_t)row*256 + c*16;
                cpa16(sb + T_K + d, Kf + go);
                cpa16(sb + T_V + d, Vf + go);
            }
            CP_COMMIT();
            CP_WAIT1();
        } else {
            CP_WAIT0();
        }
        __syncthreads();

        const uint32_t sb = sb0 + FB_ST + (kb & 1) * ST_SZ;

        #pragma unroll
        for (int i = 0; i < 8; i++)
            #pragma unroll
            for (int r = 0; r < 4; r++) sacc[i][r] = 0.f;

        #pragma unroll
        for (int kk = 0; kk < 8; kk++) {
            uint32_t q4[4];
            const uint32_t qa = sb0 + FB_Q + SWZ256(qa_off + (uint32_t)kk*32);
            ldmx4(q4[0], q4[1], q4[2], q4[3], qa);
            #pragma unroll
            for (int n16 = 0; n16 < 4; n16++) {
                uint32_t kh4[4];
                const uint32_t ka = sb + T_K +
                    SWZ256((uint32_t)((n16*16 + kb_row)*256 + kk*32 + kb_cs));
                ldmx4(kh4[0], kh4[1], kh4[2], kh4[3], ka);
                mma16816f(sacc[2*n16],   q4, &kh4[0]);
                mma16816f(sacc[2*n16+1], q4, &kh4[2]);
            }
        }

        #pragma unroll
        for (int i = 0; i < 8; i++)
            #pragma unroll
            for (int r = 0; r < 4; r++) sacc[i][r] *= sc;

        float nm0 = -1e30f, nm1 = -1e30f;
        #pragma unroll
        for (int i = 0; i < 8; i++) {
            nm0 = fmaxf(nm0, fmaxf(sacc[i][0], sacc[i][1]));
            nm1 = fmaxf(nm1, fmaxf(sacc[i][2], sacc[i][3]));
        }
        nm0 = fmaxf(nm0, __shfl_xor_sync(0xffffffffu, nm0, 1));
        nm0 = fmaxf(nm0, __shfl_xor_sync(0xffffffffu, nm0, 2));
        nm1 = fmaxf(nm1, __shfl_xor_sync(0xffffffffu, nm1, 1));
        nm1 = fmaxf(nm1, __shfl_xor_sync(0xffffffffu, nm1, 2));
        const float mn0 = fmaxf(m0, nm0), mn1 = fmaxf(m1, nm1);
        const float a0 = __expf(m0 - mn0), a1 = __expf(m1 - mn1);
        m0 = mn0; m1 = mn1;
        float ls0 = 0.f, ls1 = 0.f;
        #pragma unroll
        for (int i = 0; i < 8; i++) {
            float p0 = __expf(sacc[i][0] - m0); sacc[i][0] = p0; ls0 += p0;
            float p1 = __expf(sacc[i][1] - m0); sacc[i][1] = p1; ls0 += p1;
            float p2 = __expf(sacc[i][2] - m1); sacc[i][2] = p2; ls1 += p2;
            float p3 = __expf(sacc[i][3] - m1); sacc[i][3] = p3; ls1 += p3;
        }
        ls0 += __shfl_xor_sync(0xffffffffu, ls0, 1);
        ls0 += __shfl_xor_sync(0xffffffffu, ls0, 2);
        ls1 += __shfl_xor_sync(0xffffffffu, ls1, 1);
        ls1 += __shfl_xor_sync(0xffffffffu, ls1, 2);
        l0 = l0*a0 + ls0;
        l1 = l1*a1 + ls1;
        #pragma unroll
        for (int i = 0; i < 16; i++) {
            oacc[i][0] *= a0; oacc[i][1] *= a0;
            oacc[i][2] *= a1; oacc[i][3] *= a1;
        }

        #pragma unroll
        for (int kk = 0; kk < 4; kk++) {
            uint32_t ph[4];
            ph[0] = pack_f16(sacc[2*kk][0],   sacc[2*kk][1]);
            ph[1] = pack_f16(sacc[2*kk][2],   sacc[2*kk][3]);
            ph[2] = pack_f16(sacc[2*kk+1][0], sacc[2*kk+1][1]);
            ph[3] = pack_f16(sacc[2*kk+1][2], sacc[2*kk+1][3]);
            #pragma unroll
            for (int n16 = 0; n16 < 8; n16++) {
                uint32_t vh4[4];
                const uint32_t va = sb + T_V +
                    SWZ256((uint32_t)((kk*16 + vb_row)*256 + n16*32 + vb_cs));
                ldmx4t(vh4[0], vh4[1], vh4[2], vh4[3], va);
                mma16816f(oacc[2*n16],   ph, &vh4[0]);
                mma16816f(oacc[2*n16+1], ph, &vh4[2]);
            }
        }
    }

    // epilogue: y as single fp16, (B, S, H, hd) layout
    const int b = bh / HH, h = bh % HH;
    const int g = lane >> 2;
    const int col0 = (lane & 3) * 2;
    const float li0 = 1.0f / l0, li1 = 1.0f / l1;
    const int s0 = qb*128 + w16 + g;
    const size_t yb0 = ((size_t)(b*SS + s0)*HH + h)*HD;
    const size_t yb1 = ((size_t)(b*SS + s0 + 8)*HH + h)*HD;
    #pragma unroll
    for (int nt = 0; nt < 16; nt++) {
        const int c = nt*8 + col0;
        *(uint32_t*)(g_yf + yb0 + c) = pack_f16(oacc[nt][0]*li0, oacc[nt][1]*li0);
        *(uint32_t*)(g_yf + yb1 + c) = pack_f16(oacc[nt][2]*li1, oacc[nt][3]*li1);
    }
}

// ---------------------------------------------------------------------------
extern "C" void kernel_launch(void* const* d_in, const int* in_sizes, int n_in,
                              void* d_out, int out_size)
{
    const float* x   = (const float*)d_in[0];
    const float* ctx = (const float*)d_in[1];
    const float* cq  = (const float*)d_in[2];
    const float* sq  = (const float*)d_in[3];
    const float* ck  = (const float*)d_in[4];
    const float* sk  = (const float*)d_in[5];
    const float* Wq  = (const float*)d_in[6];
    const float* Wk  = (const float*)d_in[7];
    const float* Wv  = (const float*)d_in[8];
    const float* Wo  = (const float*)d_in[9];
    const float* qw  = (const float*)d_in[10];
    const float* kw  = (const float*)d_in[11];
    float* out = (float*)d_out;

    cudaFuncSetAttribute(qkv_kernel, cudaFuncAttributeMaxDynamicSharedMemorySize, GEMM_DSMEM);
    cudaFuncSetAttribute(wo_kernel,  cudaFuncAttributeMaxDynamicSharedMemorySize, GEMM_DSMEM);
    cudaFuncSetAttribute(flash_mma,  cudaFuncAttributeMaxDynamicSharedMemorySize, FLASH_DSMEM);

    cvt6_kernel<<<32768, 256>>>(x, ctx, Wq, Wk, Wv, Wo);

    dim3 gq3(DM/128, NROWS/128, 3);     // (16, 32, 3)
    qkv_kernel<<<gq3, 512, GEMM_DSMEM>>>();
    rms_rope_kernel<<<dim3(BB*HH*SS, 2), HD>>>(cq, sq, ck, sk, qw, kw);
    flash_mma<<<dim3(SS/128, BB*HH), 256, FLASH_DSMEM>>>();
    dim3 gg(DM/128, NROWS/128);         // (16, 32)
    wo_kernel<<<gg, 512, GEMM_DSMEM>>>(out);
}

// round 14
// speedup vs baseline: 1.5684x; 1.0433x over previous
#include <cuda_runtime.h>
#include <cuda_bf16.h>
#include <cuda_fp16.h>
#include <cstdint>

#define BB 2
#define SS 2048
#define DM 2048
#define HH 16
#define HD 128
#define NROWS (BB*SS)
// (1/sqrt(128)) * log2(e): folded into Q so softmax runs in log2 domain
#define SCLOG2E 0.12751743f

// ---------------------------------------------------------------------------
// Helpers (plain sm_80-era PTX only: ldmatrix / mma.sync / cp.async)
// ---------------------------------------------------------------------------
__device__ __forceinline__ uint32_t smem_to_u32(const void* p) {
    uint32_t a;
    asm("{ .reg .u64 t; cvta.to.shared.u64 t, %1; cvt.u32.u64 %0, t; }" : "=r"(a) : "l"(p));
    return a;
}
#define SWZ128(off) ((off) ^ (((off) >> 3) & 0x70))
#define SWZ256(off) ((off) ^ ((((off) >> 8) & 7) << 4))

__device__ __forceinline__ void cpa16(uint32_t s, const void* g) {
    asm volatile("cp.async.cg.shared.global [%0], [%1], 16;" :: "r"(s), "l"(g));
}
#define CP_COMMIT() asm volatile("cp.async.commit_group;" ::: "memory")
#define CP_WAIT2()  asm volatile("cp.async.wait_group 2;" ::: "memory")
#define CP_WAIT1()  asm volatile("cp.async.wait_group 1;" ::: "memory")
#define CP_WAIT0()  asm volatile("cp.async.wait_group 0;" ::: "memory")

__device__ __forceinline__ void ldmx4(uint32_t& r0, uint32_t& r1, uint32_t& r2, uint32_t& r3,
                                      uint32_t addr) {
    asm volatile("ldmatrix.sync.aligned.m8n8.x4.shared.b16 {%0,%1,%2,%3}, [%4];"
                 : "=r"(r0), "=r"(r1), "=r"(r2), "=r"(r3) : "r"(addr));
}
__device__ __forceinline__ void ldmx4t(uint32_t& r0, uint32_t& r1, uint32_t& r2, uint32_t& r3,
                                       uint32_t addr) {
    asm volatile("ldmatrix.sync.aligned.m8n8.x4.trans.shared.b16 {%0,%1,%2,%3}, [%4];"
                 : "=r"(r0), "=r"(r1), "=r"(r2), "=r"(r3) : "r"(addr));
}
__device__ __forceinline__ void mma16816f(float* c, const uint32_t* a, const uint32_t* b) {
    asm volatile("mma.sync.aligned.m16n8k16.row.col.f32.f16.f16.f32 "
                 "{%0,%1,%2,%3}, {%4,%5,%6,%7}, {%8,%9}, {%0,%1,%2,%3};"
                 : "+f"(c[0]), "+f"(c[1]), "+f"(c[2]), "+f"(c[3])
                 : "r"(a[0]), "r"(a[1]), "r"(a[2]), "r"(a[3]), "r"(b[0]), "r"(b[1]));
}

__device__ __forceinline__ uint32_t pack_f16(float a, float b) {
    __half2 t = __floats2half2_rn(a, b);
    return *(uint32_t*)&t;
}
__device__ __forceinline__ float fexp2(float x) {
    float y;
    asm("ex2.approx.ftz.f32 %0, %1;" : "=f"(y) : "f"(x));
    return y;
}

// ---------------------------------------------------------------------------
// Device scratch (all GEMM/flash operands single fp16)
// ---------------------------------------------------------------------------
__device__ __align__(256) float g_q[(size_t)BB*HH*SS*HD];
__device__ __align__(256) float g_k[(size_t)BB*HH*SS*HD];
__device__ __align__(256) __half g_xf[(size_t)NROWS*DM];
__device__ __align__(256) __half g_cf[(size_t)NROWS*DM];
__device__ __align__(256) __half g_wqh[DM*DM], g_wkh[DM*DM], g_wvh[DM*DM], g_woh[DM*DM];
__device__ __align__(256) __half g_yf[(size_t)NROWS*DM];
__device__ __align__(256) __half g_qf[(size_t)BB*HH*SS*HD];
__device__ __align__(256) __half g_kf[(size_t)BB*HH*SS*HD];
__device__ __align__(256) __half g_vf[(size_t)BB*HH*SS*HD];

// ---------------------------------------------------------------------------
// Fused fp32 -> fp16 single-RN conversion for all 6 tensors.
// ---------------------------------------------------------------------------
__global__ void cvt6_kernel(const float* __restrict__ x, const float* __restrict__ ctx,
                            const float* __restrict__ Wq, const float* __restrict__ Wk,
                            const float* __restrict__ Wv, const float* __restrict__ Wo)
{
    int bid = blockIdx.x;
    const float* src;
    __half* dst;
    int lb;
    if (bid < 8192)       { src = x;   dst = g_xf;  lb = bid; }
    else if (bid < 16384) { src = ctx; dst = g_cf;  lb = bid - 8192; }
    else if (bid < 20480) { src = Wq;  dst = g_wqh; lb = bid - 16384; }
    else if (bid < 24576) { src = Wk;  dst = g_wkh; lb = bid - 20480; }
    else if (bid < 28672) { src = Wv;  dst = g_wvh; lb = bid - 24576; }
    else                  { src = Wo;  dst = g_woh; lb = bid - 28672; }
    const int i = lb*256 + threadIdx.x;
    float4 v = ((const float4*)src)[i];
    ((uint2*)dst)[i] = make_uint2(pack_f16(v.x, v.y), pack_f16(v.z, v.w));
}

// ---------------------------------------------------------------------------
// 4-stage single-product fp16 GEMM mainloop, 16 warps, warp tile 32x32.
// ---------------------------------------------------------------------------
#define KC 64
#define NSTG (DM/KC)
#define A_OFF 0
#define B_OFF 16384
#define STG_BYTES 32768
#define NBUF 4
#define GEMM_DSMEM (NBUF*STG_BYTES + 1024)

__device__ __forceinline__ void gemm_body(
    const __half* __restrict__ Ah, const __half* __restrict__ Bh,
    uint32_t sbase, int m0, int n0, float acc[2][4][4])
{
    const int tid = threadIdx.x;
    const int wid = tid >> 5;
    const int lane = tid & 31;
    const int warp_m = wid >> 2;
    const int warp_n = wid & 3;

    const int prow = tid >> 2;
    const int pq = tid & 3;
    const size_t gA = (size_t)(m0 + prow) * DM + pq * 16;
    const size_t gB = (size_t)(n0 + prow) * DM + pq * 16;
    const uint32_t swp[2] = {
        SWZ128((uint32_t)(prow*128 + (pq*2 + 0)*16)),
        SWZ128((uint32_t)(prow*128 + (pq*2 + 1)*16)) };

    #pragma unroll
    for (int s = 0; s < 3; s++) {
        const uint32_t buf = sbase + s * STG_BYTES;
        const size_t ko = (size_t)s * KC;
        #pragma unroll
        for (int c = 0; c < 2; c++) {
            const size_t go = ko + (size_t)c * 8;
            cpa16(buf + A_OFF + swp[c], Ah + gA + go);
            cpa16(buf + B_OFF + swp[c], Bh + gB + go);
        }
        CP_COMMIT();
    }

    const int a_r = warp_m*32 + (lane & 15);
    const int a_cs = lane >> 4;
    const int b_r = warp_n*32 + ((lane >> 4) << 3) + (lane & 7);
    const int b_cs = (lane >> 3) & 1;

    int sbuf = 0;
    for (int s = 0; s < NSTG; s++) {
        CP_WAIT2();
        __syncthreads();
        if (s + 3 < NSTG) {
            const uint32_t buf = sbase + ((sbuf + 3) & 3) * STG_BYTES;
            const size_t ko = (size_t)(s+3) * KC;
            #pragma unroll
            for (int c = 0; c < 2; c++) {
                const size_t go = ko + (size_t)c * 8;
                cpa16(buf + A_OFF + swp[c], Ah + gA + go);
                cpa16(buf + B_OFF + swp[c], Bh + gB + go);
            }
            CP_COMMIT();
        }

        const uint32_t buf = sbase + sbuf * STG_BYTES;
        #pragma unroll
        for (int ks = 0; ks < 4; ks++) {
            const int kc = ks * 2;
            uint32_t ah[2][4], bh[4][2];
            #pragma unroll
            for (int mt = 0; mt < 2; mt++) {
                const uint32_t off = (uint32_t)((a_r + mt*16)*128 + (kc + a_cs)*16);
                ldmx4(ah[mt][0], ah[mt][1], ah[mt][2], ah[mt][3], buf + A_OFF + SWZ128(off));
            }
            #pragma unroll
            for (int np = 0; np < 2; np++) {
                const uint32_t off = (uint32_t)((b_r + np*16)*128 + (kc + b_cs)*16);
                ldmx4(bh[np*2][0], bh[np*2][1], bh[np*2+1][0], bh[np*2+1][1],
                      buf + B_OFF + SWZ128(off));
            }
            #pragma unroll
            for (int mt = 0; mt < 2; mt++)
                #pragma unroll
                for (int nt = 0; nt < 4; nt++)
                    mma16816f(acc[mt][nt], ah[mt], bh[nt]);
        }
        sbuf = (sbuf + 1) & 3;
    }
}

// ---------------------------------------------------------------------------
// Fused Q/K/V projection: blockIdx.z selects operand set + epilogue.
// ---------------------------------------------------------------------------
__global__ __launch_bounds__(512, 1)
void qkv_kernel()
{
    extern __shared__ char dsm_raw[];
    const uint32_t raw_u = smem_to_u32(dsm_raw);
    const uint32_t sbase = (raw_u + 1023u) & ~1023u;

    const int z = blockIdx.z;
    const __half *Ah, *Bh;
    if (z == 0)      { Ah = g_xf; Bh = g_wqh; }
    else if (z == 1) { Ah = g_cf; Bh = g_wkh; }
    else             { Ah = g_cf; Bh = g_wvh; }

    const int m0 = blockIdx.y * 128;
    const int n0 = blockIdx.x * 128;

    float acc[2][4][4];
    #pragma unroll
    for (int i = 0; i < 2; i++)
        #pragma unroll
        for (int j = 0; j < 4; j++)
            #pragma unroll
            for (int r = 0; r < 4; r++) acc[i][j][r] = 0.f;

    gemm_body(Ah, Bh, sbase, m0, n0, acc);

    const int tid = threadIdx.x;
    const int wid = tid >> 5;
    const int lane = tid & 31;
    const int warp_m = wid >> 2;
    const int warp_n = wid & 3;

    #pragma unroll
    for (int mt = 0; mt < 2; mt++) {
        const int mrow = m0 + warp_m*32 + mt*16 + (lane >> 2);
        #pragma unroll
        for (int half = 0; half < 2; half++) {
            const int m = mrow + half*8;
            const int b = m >> 11, sidx = m & (SS - 1);
            const size_t rb = ((size_t)((b*HH + blockIdx.x)*SS + sidx))*HD;
            #pragma unroll
            for (int nt = 0; nt < 4; nt++) {
                const int nn = warp_n*32 + nt*8 + 2*(lane & 3);
                float vx = half ? acc[mt][nt][2] : acc[mt][nt][0];
                float vy = half ? acc[mt][nt][3] : acc[mt][nt][1];
                if (z == 0) {
                    *(float2*)(g_q + rb + nn) = make_float2(vx, vy);
                } else if (z == 1) {
                    *(float2*)(g_k + rb + nn) = make_float2(vx, vy);
                } else {
                    *(uint32_t*)(g_vf + rb + nn) = pack_f16(vx, vy);
                }
            }
        }
    }
}

// ---------------------------------------------------------------------------
// Output projection: out = y @ Wo^T, fp32 result.
// ---------------------------------------------------------------------------
__global__ __launch_bounds__(512, 1)
void wo_kernel(float* __restrict__ C)
{
    extern __shared__ char dsm_raw[];
    const uint32_t raw_u = smem_to_u32(dsm_raw);
    const uint32_t sbase = (raw_u + 1023u) & ~1023u;

    const int m0 = blockIdx.y * 128;
    const int n0 = blockIdx.x * 128;

    float acc[2][4][4];
    #pragma unroll
    for (int i = 0; i < 2; i++)
        #pragma unroll
        for (int j = 0; j < 4; j++)
            #pragma unroll
            for (int r = 0; r < 4; r++) acc[i][j][r] = 0.f;

    gemm_body(g_yf, g_woh, sbase, m0, n0, acc);

    const int tid = threadIdx.x;
    const int wid = tid >> 5;
    const int lane = tid & 31;
    const int warp_m = wid >> 2;
    const int warp_n = wid & 3;

    #pragma unroll
    for (int mt = 0; mt < 2; mt++) {
        const int mrow = m0 + warp_m*32 + mt*16 + (lane >> 2);
        #pragma unroll
        for (int half = 0; half < 2; half++) {
            const int m = mrow + half*8;
            #pragma unroll
            for (int nt = 0; nt < 4; nt++) {
                const int nn = warp_n*32 + nt*8 + 2*(lane & 3);
                float vx = half ? acc[mt][nt][2] : acc[mt][nt][0];
                float vy = half ? acc[mt][nt][3] : acc[mt][nt][1];
                *(float2*)(C + (size_t)m*DM + n0 + nn) = make_float2(vx, vy);
            }
        }
    }
}

// ---------------------------------------------------------------------------
// RMS norm + RoPE, warp-per-row (no smem, no block syncs).
// 256 threads = 8 warps = 8 rows per block. Q output pre-scaled by SCLOG2E.
// Lane l holds elems 4l..4l+3; rotate-half partner lives at lane l^16.
// ---------------------------------------------------------------------------
__global__ __launch_bounds__(256)
void rms_rope_kernel(const float* __restrict__ cq, const float* __restrict__ sq,
                     const float* __restrict__ ck, const float* __restrict__ sk,
                     const float* __restrict__ qw, const float* __restrict__ kw)
{
    const int isk = blockIdx.y;
    const int wid = threadIdx.x >> 5;
    const int lane = threadIdx.x & 31;
    const int row = blockIdx.x * 8 + wid;          // (b*HH + h)*SS + s
    const float* data = isk ? g_k : g_q;
    const float* cp = isk ? ck : cq;
    const float* sp = isk ? sk : sq;
    const float* w  = isk ? kw : qw;
    __half* outp = isk ? g_kf : g_qf;
    const int s = row & (SS - 1);
    const int b = row >> 15;                       // HH*SS = 32768

    const size_t rbase = (size_t)row * HD;
    float4 v = *(const float4*)(data + rbase + lane*4);
    float s2 = v.x*v.x + v.y*v.y + v.z*v.z + v.w*v.w;
    #pragma unroll
    for (int o = 16; o; o >>= 1) s2 += __shfl_xor_sync(0xffffffffu, s2, o);
    const float rinv = rsqrtf(s2 * (1.0f/HD) + 1e-6f);

    float4 wv = *(const float4*)(w + lane*4);
    float qn0 = v.x * rinv * wv.x;
    float qn1 = v.y * rinv * wv.y;
    float qn2 = v.z * rinv * wv.z;
    float qn3 = v.w * rinv * wv.w;

    const float sg = (lane < 16) ? -1.f : 1.f;
    const float r0 = sg * __shfl_xor_sync(0xffffffffu, qn0, 16);
    const float r1 = sg * __shfl_xor_sync(0xffffffffu, qn1, 16);
    const float r2 = sg * __shfl_xor_sync(0xffffffffu, qn2, 16);
    const float r3 = sg * __shfl_xor_sync(0xffffffffu, qn3, 16);

    const size_t ci = ((size_t)(b*SS + s)) * HD + lane*4;
    float4 c4 = *(const float4*)(cp + ci);
    float4 s4 = *(const float4*)(sp + ci);
    float o0 = qn0*c4.x + r0*s4.x;
    float o1 = qn1*c4.y + r1*s4.y;
    float o2 = qn2*c4.z + r2*s4.z;
    float o3 = qn3*c4.w + r3*s4.w;
    if (!isk) { o0 *= SCLOG2E; o1 *= SCLOG2E; o2 *= SCLOG2E; o3 *= SCLOG2E; }
    *(uint2*)(outp + rbase + lane*4) = make_uint2(pack_f16(o0, o1), pack_f16(o2, o3));
}

// ---------------------------------------------------------------------------
// Flash attention, single fp16 operands; softmax in log2-domain (scale folded
// into Q), ex2.approx, vote-skipped O-rescale.
// ---------------------------------------------------------------------------
#define FB_Q 0
#define FB_ST 32768
#define ST_SZ 32768
#define T_K 0
#define T_V 16384
#define NKB (SS/64)
#define FLASH_DSMEM (FB_ST + 2*ST_SZ + 1024)

__global__ __launch_bounds__(256, 1)
void flash_mma()
{
    extern __shared__ char fsm_raw[];
    const uint32_t raw_u = smem_to_u32(fsm_raw);
    const uint32_t sb0 = (raw_u + 1023u) & ~1023u;
    char* bp = fsm_raw + (sb0 - raw_u);

    const int tid = threadIdx.x;
    const int wid = tid >> 5;
    const int lane = tid & 31;
    const int qb = blockIdx.x;
    const int bh = blockIdx.y;

    const size_t base = (size_t)bh * SS * HD;
    const char* Qf = (const char*)(g_qf + base + (size_t)qb * 128 * HD);
    const char* Kf = (const char*)(g_kf + base);
    const char* Vf = (const char*)(g_vf + base);

    #pragma unroll
    for (int i = 0; i < 8; i++) {
        const int idx = tid + i*256;
        const int row = idx >> 4, c = idx & 15;
        const uint32_t d = SWZ256((uint32_t)(row*256 + c*16));
        *(uint4*)(bp + FB_Q + d) = *(const uint4*)(Qf + (size_t)row*256 + c*16);
    }

    {
        const uint32_t sb = sb0 + FB_ST;
        #pragma unroll
        for (int j = 0; j < 4; j++) {
            const int idx = tid + j*256;
            const int row = idx >> 4, c = idx & 15;
            const uint32_t d = SWZ256((uint32_t)(row*256 + c*16));
            const size_t go = (size_t)row*256 + c*16;
            cpa16(sb + T_K + d, Kf + go);
            cpa16(sb + T_V + d, Vf + go);
        }
        CP_COMMIT();
    }

    float sacc[8][4];
    float oacc[16][4];
    #pragma unroll
    for (int i = 0; i < 16; i++)
        #pragma unroll
        for (int r = 0; r < 4; r++) oacc[i][r] = 0.f;
    float m0 = -1e30f, m1 = -1e30f, l0 = 0.f, l1 = 0.f;

    const int w16 = wid * 16;
    const uint32_t qa_off = (uint32_t)((w16 + (lane & 15))*256 + (lane >> 4)*16);
    const uint32_t kb_row = (uint32_t)(((lane >> 4) << 3) + (lane & 7));
    const uint32_t kb_cs = (uint32_t)(((lane >> 3) & 1) * 16);
    const uint32_t vb_row = (uint32_t)((lane & 7) + (((lane >> 3) & 1) << 3));
    const uint32_t vb_cs = (uint32_t)((lane >> 4) * 16);

    for (int kb = 0; kb < NKB; kb++) {
        if (kb > 0) __syncthreads();
        if (kb + 1 < NKB) {
            const uint32_t sb = sb0 + FB_ST + ((kb+1) & 1) * ST_SZ;
            const size_t kbase = (size_t)(kb+1) * 64 * 256;
            #pragma unroll
            for (int j = 0; j < 4; j++) {
                const int idx = tid + j*256;
                const int row = idx >> 4, c = idx & 15;
                const uint32_t d = SWZ256((uint32_t)(row*256 + c*16));
                const size_t go = kbase + (size_t)row*256 + c*16;
                cpa16(sb + T_K + d, Kf + go);
                cpa16(sb + T_V + d, Vf + go);
            }
            CP_COMMIT();
            CP_WAIT1();
        } else {
            CP_WAIT0();
        }
        __syncthreads();

        const uint32_t sb = sb0 + FB_ST + (kb & 1) * ST_SZ;

        // ---- S = Q K^T (Q pre-scaled by sc*log2e; S is in log2 units)
        #pragma unroll
        for (int i = 0; i < 8; i++)
            #pragma unroll
            for (int r = 0; r < 4; r++) sacc[i][r] = 0.f;

        #pragma unroll
        for (int kk = 0; kk < 8; kk++) {
            uint32_t q4[4];
            const uint32_t qa = sb0 + FB_Q + SWZ256(qa_off + (uint32_t)kk*32);
            ldmx4(q4[0], q4[1], q4[2], q4[3], qa);
            #pragma unroll
            for (int n16 = 0; n16 < 4; n16++) {
                uint32_t kh4[4];
                const uint32_t ka = sb + T_K +
                    SWZ256((uint32_t)((n16*16 + kb_row)*256 + kk*32 + kb_cs));
                ldmx4(kh4[0], kh4[1], kh4[2], kh4[3], ka);
                mma16816f(sacc[2*n16],   q4, &kh4[0]);
                mma16816f(sacc[2*n16+1], q4, &kh4[2]);
            }
        }

        // ---- online softmax (log2 domain, warp-local)
        float nm0 = -1e30f, nm1 = -1e30f;
        #pragma unroll
        for (int i = 0; i < 8; i++) {
            nm0 = fmaxf(nm0, fmaxf(sacc[i][0], sacc[i][1]));
            nm1 = fmaxf(nm1, fmaxf(sacc[i][2], sacc[i][3]));
        }
        nm0 = fmaxf(nm0, __shfl_xor_sync(0xffffffffu, nm0, 1));
        nm0 = fmaxf(nm0, __shfl_xor_sync(0xffffffffu, nm0, 2));
        nm1 = fmaxf(nm1, __shfl_xor_sync(0xffffffffu, nm1, 1));
        nm1 = fmaxf(nm1, __shfl_xor_sync(0xffffffffu, nm1, 2));
        const float mn0 = fmaxf(m0, nm0), mn1 = fmaxf(m1, nm1);
        const float a0 = fexp2(m0 - mn0), a1 = fexp2(m1 - mn1);
        m0 = mn0; m1 = mn1;
        float ls0 = 0.f, ls1 = 0.f;
        #pragma unroll
        for (int i = 0; i < 8; i++) {
            float p0 = fexp2(sacc[i][0] - m0); sacc[i][0] = p0; ls0 += p0;
            float p1 = fexp2(sacc[i][1] - m0); sacc[i][1] = p1; ls0 += p1;
            float p2 = fexp2(sacc[i][2] - m1); sacc[i][2] = p2; ls1 += p2;
            float p3 = fexp2(sacc[i][3] - m1); sacc[i][3] = p3; ls1 += p3;
        }
        ls0 += __shfl_xor_sync(0xffffffffu, ls0, 1);
        ls0 += __shfl_xor_sync(0xffffffffu, ls0, 2);
        ls1 += __shfl_xor_sync(0xffffffffu, ls1, 1);
        ls1 += __shfl_xor_sync(0xffffffffu, ls1, 2);
        l0 = l0*a0 + ls0;
        l1 = l1*a1 + ls1;
        // rescale O only if some row's max actually moved (a != 1.0)
        if (__any_sync(0xffffffffu, (a0 != 1.f) || (a1 != 1.f))) {
            #pragma unroll
            for (int i = 0; i < 16; i++) {
                oacc[i][0] *= a0; oacc[i][1] *= a0;
                oacc[i][2] *= a1; oacc[i][3] *= a1;
            }
        }

        // ---- O += P V (single product)
        #pragma unroll
        for (int kk = 0; kk < 4; kk++) {
            uint32_t ph[4];
            ph[0] = pack_f16(sacc[2*kk][0],   sacc[2*kk][1]);
            ph[1] = pack_f16(sacc[2*kk][2],   sacc[2*kk][3]);
            ph[2] = pack_f16(sacc[2*kk+1][0], sacc[2*kk+1][1]);
            ph[3] = pack_f16(sacc[2*kk+1][2], sacc[2*kk+1][3]);
            #pragma unroll
            for (int n16 = 0; n16 < 8; n16++) {
                uint32_t vh4[4];
                const uint32_t va = sb + T_V +
                    SWZ256((uint32_t)((kk*16 + vb_row)*256 + n16*32 + vb_cs));
                ldmx4t(vh4[0], vh4[1], vh4[2], vh4[3], va);
                mma16816f(oacc[2*n16],   ph, &vh4[0]);
                mma16816f(oacc[2*n16+1], ph, &vh4[2]);
            }
        }
    }

    // epilogue: y as single fp16, (B, S, H, hd) layout
    const int b = bh / HH, h = bh % HH;
    const int g = lane >> 2;
    const int col0 = (lane & 3) * 2;
    const float li0 = 1.0f / l0, li1 = 1.0f / l1;
    const int s0 = qb*128 + w16 + g;
    const size_t yb0 = ((size_t)(b*SS + s0)*HH + h)*HD;
    const size_t yb1 = ((size_t)(b*SS + s0 + 8)*HH + h)*HD;
    #pragma unroll
    for (int nt = 0; nt < 16; nt++) {
        const int c = nt*8 + col0;
        *(uint32_t*)(g_yf + yb0 + c) = pack_f16(oacc[nt][0]*li0, oacc[nt][1]*li0);
        *(uint32_t*)(g_yf + yb1 + c) = pack_f16(oacc[nt][2]*li1, oacc[nt][3]*li1);
    }
}

// ---------------------------------------------------------------------------
extern "C" void kernel_launch(void* const* d_in, const int* in_sizes, int n_in,
                              void* d_out, int out_size)
{
    const float* x   = (const float*)d_in[0];
    const float* ctx = (const float*)d_in[1];
    const float* cq  = (const float*)d_in[2];
    const float* sq  = (const float*)d_in[3];
    const float* ck  = (const float*)d_in[4];
    const float* sk  = (const float*)d_in[5];
    const float* Wq  = (const float*)d_in[6];
    const float* Wk  = (const float*)d_in[7];
    const float* Wv  = (const float*)d_in[8];
    const float* Wo  = (const float*)d_in[9];
    const float* qw  = (const float*)d_in[10];
    const float* kw  = (const float*)d_in[11];
    float* out = (float*)d_out;

    cudaFuncSetAttribute(qkv_kernel, cudaFuncAttributeMaxDynamicSharedMemorySize, GEMM_DSMEM);
    cudaFuncSetAttribute(wo_kernel,  cudaFuncAttributeMaxDynamicSharedMemorySize, GEMM_DSMEM);
    cudaFuncSetAttribute(flash_mma,  cudaFuncAttributeMaxDynamicSharedMemorySize, FLASH_DSMEM);

    cvt6_kernel<<<32768, 256>>>(x, ctx, Wq, Wk, Wv, Wo);

    dim3 gq3(DM/128, NROWS/128, 3);     // (16, 32, 3)
    qkv_kernel<<<gq3, 512, GEMM_DSMEM>>>();
    rms_rope_kernel<<<dim3(BB*HH*SS/8, 2), 256>>>(cq, sq, ck, sk, qw, kw);
    flash_mma<<<dim3(SS/128, BB*HH), 256, FLASH_DSMEM>>>();
    dim3 gg(DM/128, NROWS/128);         // (16, 32)
    wo_kernel<<<gg, 512, GEMM_DSMEM>>>(out);
}